// round 5
// baseline (speedup 1.0000x reference)
#include <cuda_runtime.h>
#include <cstddef>

// NNUE evaluator, fused single kernel. 256 threads/block, 1 block/SM,
// 4-way position-interleaved gather (16 LDG.128 in flight per thread).
// d_in: 0 white_idx [B,32] (int32/int64 runtime detected)  1 black_idx
//       2 w_ft [45056,512] f32  3 b_ft[512]  4 w1[1024,32] 5 b1[32]
//       6 w2[32,32] 7 b2[32] 8 w3[32,1] 9 b3[1]
// d_out: features [B,1024] f32 followed by values [B] f32.

#define NC4      128
#define NFEAT    1024
#define NACT     32
#define H1       32
#define W1TS     1025         // padded row stride for transposed w1 in smem
#define PB       16           // positions per batch phase
#define PH       8            // positions per layer-1 pass
#define X1S      33
#define NTHR     256

#define SMEM_FLOATS (PB*NFEAT + H1*W1TS + 1024 + PB*X1S + 96 + PB*64)
#define SMEM_BYTES  (SMEM_FLOATS * 4)

__global__ __launch_bounds__(NTHR, 1)
void nnue_fused_kernel(const void* __restrict__ widx_raw,
                       const void* __restrict__ bidx_raw,
                       const float* __restrict__ w_ft,
                       const float* __restrict__ b_ft,
                       const float* __restrict__ w1,
                       const float* __restrict__ b1,
                       const float* __restrict__ w2,
                       const float* __restrict__ b2,
                       const float* __restrict__ w3,
                       const float* __restrict__ b3,
                       float* __restrict__ out_feat,
                       float* __restrict__ out_val,
                       int Bn)
{
    extern __shared__ float smem[];
    float* feat = smem;                         // PB*1024
    float* w1T  = feat + PB*NFEAT;              // 32*1025
    float* w2s  = w1T + H1*W1TS;                // 1024
    float* x1s  = w2s + 1024;                   // PB*33
    float* b1s  = x1s + PB*X1S;                 // 32
    float* b2s  = b1s + 32;                     // 32
    float* w3s  = b2s + 32;                     // 32
    int*   idxs = (int*)(w3s + 32);             // PB*64

    const int tid  = threadIdx.x;
    const int lane = tid & 31;
    const int wid  = tid >> 5;

    // ---- one-time staging ----
    for (int e = tid; e < NFEAT * H1; e += NTHR) {
        int i = e >> 5;
        int j = e & 31;
        w1T[j * W1TS + i] = w1[e];
    }
    for (int e = tid; e < H1 * H1; e += NTHR) w2s[e] = w2[e];
    if (tid < 32) {
        b1s[tid] = b1[tid];
        b2s[tid] = b2[tid];
        w3s[tid] = w3[tid];
    }

    const int is64 = (__ldg((const int*)widx_raw + 1) == 0) ? 1 : 0;
    const float b3v = __ldg(b3);

    const int side = tid >> 7;       // 0 white, 1 black
    const int c    = tid & 127;      // float4 column within perspective
    const float4* __restrict__ wft4 = (const float4*)w_ft;
    const float4 bias = ((const float4*)b_ft)[c];

    // contiguous position range per block
    const int grid = gridDim.x;
    const int base = Bn / grid, rem = Bn % grid;
    const int bid  = blockIdx.x;
    int start, count;
    if (bid < rem) { count = base + 1; start = bid * count; }
    else           { count = base;     start = rem * (base + 1) + (bid - rem) * base; }

    __syncthreads();

    for (int off = 0; off < count; off += PB) {
        const int pos0 = start + off;
        const int npos = (count - off < PB) ? (count - off) : PB;

        // ---- index load (premultiplied by NC4) ----
        const int nIdx = npos * 64;
        for (int e = tid; e < nIdx; e += NTHR) {
            const int p = e >> 6, t = e & 63;
            const void* src = (t < 32) ? widx_raw : bidx_raw;
            const long long g = (long long)(pos0 + p) * NACT + (t & 31);
            int r;
            if (is64) r = (int)((const long long*)src)[g];
            else      r = ((const int*)src)[g];
            idxs[e] = r * NC4;
        }
        __syncthreads();

        // ---- gather: 4 positions interleaved, 16 LDG.128 in flight ----
        for (int p0 = 0; p0 < npos; p0 += 4) {
            bool has[4];
            const int* __restrict__ ip[4];
            #pragma unroll
            for (int q = 0; q < 4; q++) {
                has[q] = (p0 + q) < npos;
                ip[q] = idxs + (has[q] ? (p0 + q) : 0) * 64 + side * NACT;
            }
            float4 acc[4];
            #pragma unroll
            for (int q = 0; q < 4; q++) acc[q] = bias;

            #pragma unroll
            for (int a = 0; a < NACT; a += 4) {
                float4 v[4][4];
                #pragma unroll
                for (int q = 0; q < 4; q++)
                    #pragma unroll
                    for (int u = 0; u < 4; u++)
                        v[q][u] = wft4[ip[q][a + u] + c];
                #pragma unroll
                for (int q = 0; q < 4; q++)
                    #pragma unroll
                    for (int u = 0; u < 4; u++) {
                        acc[q].x += v[q][u].x; acc[q].y += v[q][u].y;
                        acc[q].z += v[q][u].z; acc[q].w += v[q][u].w;
                    }
            }
            #pragma unroll
            for (int q = 0; q < 4; q++) {
                if (has[q]) {
                    float4 a0 = acc[q];
                    a0.x = fmaxf(a0.x, 0.f); a0.y = fmaxf(a0.y, 0.f);
                    a0.z = fmaxf(a0.z, 0.f); a0.w = fmaxf(a0.w, 0.f);
                    ((float4*)feat)[(p0 + q) * 256 + tid] = a0;
                    ((float4*)(out_feat + (size_t)(pos0 + p0 + q) * NFEAT))[tid] = a0;
                }
            }
        }
        __syncthreads();

        // ---- layer 1: warp w owns outputs 4w..4w+3; two passes of 8 positions ----
        {
            const int j0 = wid * 4;
            for (int pbase = 0; pbase < npos; pbase += PH) {
                float acc0[PH], acc1[PH], acc2[PH], acc3[PH];
                #pragma unroll
                for (int pp = 0; pp < PH; pp++) { acc0[pp]=0.f; acc1[pp]=0.f; acc2[pp]=0.f; acc3[pp]=0.f; }

                #pragma unroll
                for (int kk = 0; kk < 8; kk++) {        // i-chunks of 128
                    float wr0[4], wr1[4], wr2[4], wr3[4];
                    #pragma unroll
                    for (int k = 0; k < 4; k++) {
                        const int i = lane + 32 * (4 * kk + k);
                        wr0[k] = w1T[(j0 + 0) * W1TS + i];
                        wr1[k] = w1T[(j0 + 1) * W1TS + i];
                        wr2[k] = w1T[(j0 + 2) * W1TS + i];
                        wr3[k] = w1T[(j0 + 3) * W1TS + i];
                    }
                    #pragma unroll
                    for (int pp = 0; pp < PH; pp++) {
                        const int p = pbase + pp;
                        if (p < npos) {
                            #pragma unroll
                            for (int k = 0; k < 4; k++) {
                                const float f = feat[p * NFEAT + lane + 32 * (4 * kk + k)];
                                acc0[pp] = fmaf(f, wr0[k], acc0[pp]);
                                acc1[pp] = fmaf(f, wr1[k], acc1[pp]);
                                acc2[pp] = fmaf(f, wr2[k], acc2[pp]);
                                acc3[pp] = fmaf(f, wr3[k], acc3[pp]);
                            }
                        }
                    }
                }
                #pragma unroll
                for (int pp = 0; pp < PH; pp++) {
                    const int p = pbase + pp;
                    if (p < npos) {
                        float s0 = acc0[pp], s1 = acc1[pp], s2 = acc2[pp], s3 = acc3[pp];
                        #pragma unroll
                        for (int o = 16; o; o >>= 1) {
                            s0 += __shfl_xor_sync(0xffffffffu, s0, o);
                            s1 += __shfl_xor_sync(0xffffffffu, s1, o);
                            s2 += __shfl_xor_sync(0xffffffffu, s2, o);
                            s3 += __shfl_xor_sync(0xffffffffu, s3, o);
                        }
                        if (lane == 0) {
                            x1s[p * X1S + j0 + 0] = fmaxf(s0 + b1s[j0 + 0], 0.f);
                            x1s[p * X1S + j0 + 1] = fmaxf(s1 + b1s[j0 + 1], 0.f);
                            x1s[p * X1S + j0 + 2] = fmaxf(s2 + b1s[j0 + 2], 0.f);
                            x1s[p * X1S + j0 + 3] = fmaxf(s3 + b1s[j0 + 3], 0.f);
                        }
                    }
                }
            }
        }
        __syncthreads();

        // ---- layers 2+3: one warp per position ----
        for (int p = wid; p < npos; p += 8) {
            float s = b2s[lane];
            #pragma unroll
            for (int i = 0; i < H1; i++)
                s = fmaf(x1s[p * X1S + i], w2s[i * H1 + lane], s);
            s = fmaxf(s, 0.f);
            float v = s * w3s[lane];
            #pragma unroll
            for (int o = 16; o; o >>= 1)
                v += __shfl_xor_sync(0xffffffffu, v, o);
            if (lane == 0)
                out_val[pos0 + p] = (v + b3v) * 100.0f;
        }
        __syncthreads();
    }
}

extern "C" void kernel_launch(void* const* d_in, const int* in_sizes, int n_in,
                              void* d_out, int out_size)
{
    (void)n_in; (void)out_size;
    const void*  widx = d_in[0];
    const void*  bidx = d_in[1];
    const float* w_ft = (const float*)d_in[2];
    const float* b_ft = (const float*)d_in[3];
    const float* w1   = (const float*)d_in[4];
    const float* b1   = (const float*)d_in[5];
    const float* w2   = (const float*)d_in[6];
    const float* b2   = (const float*)d_in[7];
    const float* w3   = (const float*)d_in[8];
    const float* b3   = (const float*)d_in[9];

    const int Bn = in_sizes[0] / NACT;

    float* out_feat = (float*)d_out;
    float* out_val  = out_feat + (size_t)Bn * NFEAT;

    cudaFuncSetAttribute(nnue_fused_kernel,
                         cudaFuncAttributeMaxDynamicSharedMemorySize,
                         SMEM_BYTES);

    int dev = 0, nsm = 148;
    cudaGetDevice(&dev);
    cudaDeviceGetAttribute(&nsm, cudaDevAttrMultiProcessorCount, dev);
    if (nsm <= 0) nsm = 148;
    int grid = nsm;
    if (grid > Bn) grid = Bn;

    nnue_fused_kernel<<<grid, NTHR, SMEM_BYTES>>>(
        widx, bidx, w_ft, b_ft, w1, b1, w2, b2, w3, b3,
        out_feat, out_val, Bn);
}

// round 8
// speedup vs baseline: 1.1653x; 1.1653x over previous
#include <cuda_runtime.h>
#include <cuda_fp16.h>
#include <cstddef>

// NNUE evaluator: fp16-converted feature table + fused eval kernel.
// d_in: 0 white_idx [B,32] (int32/int64 runtime detected)  1 black_idx
//       2 w_ft [45056,512] f32  3 b_ft[512]  4 w1[1024,32] 5 b1[32]
//       6 w2[32,32] 7 b2[32] 8 w3[32,1] 9 b3[1]
// d_out: features [B,1024] f32 followed by values [B] f32.

#define F_DIM    45056
#define ACCW     512
#define NFEAT    1024
#define NACT     32
#define H1       32
#define W1TS     1025
#define PB       16
#define X1S      33
#define NTHR     256
#define ROW_U4   64            // uint4 (8 halves) per 512-wide row

// fp16 feature table scratch (46 MB)
__device__ __align__(16) __half g_wft_h[(size_t)F_DIM * ACCW];

#define SMEM_FLOATS (PB*NFEAT + H1*W1TS + 1024 + PB*X1S + 96 + PB*64)
#define SMEM_BYTES  (SMEM_FLOATS * 4)

static __device__ __forceinline__ unsigned h2u(__half2 h) {
    unsigned u;
    memcpy(&u, &h, 4);
    return u;
}

// ---- conversion kernel: w_ft f32 -> g_wft_h fp16 ----
__global__ __launch_bounds__(1024, 2)
void convert_kernel(const float4* __restrict__ src)
{
    const int n8 = (F_DIM * ACCW) / 8;       // uint4 elements
    uint4* __restrict__ dst = (uint4*)g_wft_h;
    const int stride = gridDim.x * blockDim.x;
    for (int i = blockIdx.x * blockDim.x + threadIdx.x; i < n8; i += stride) {
        float4 a = src[2 * i];
        float4 b = src[2 * i + 1];
        uint4 o;
        o.x = h2u(__floats2half2_rn(a.x, a.y));
        o.y = h2u(__floats2half2_rn(a.z, a.w));
        o.z = h2u(__floats2half2_rn(b.x, b.y));
        o.w = h2u(__floats2half2_rn(b.z, b.w));
        dst[i] = o;
    }
}

__global__ __launch_bounds__(NTHR, 1)
void nnue_fused_kernel(const void* __restrict__ widx_raw,
                       const void* __restrict__ bidx_raw,
                       const float* __restrict__ b_ft,
                       const float* __restrict__ w1,
                       const float* __restrict__ b1,
                       const float* __restrict__ w2,
                       const float* __restrict__ b2,
                       const float* __restrict__ w3,
                       const float* __restrict__ b3,
                       float* __restrict__ out_feat,
                       float* __restrict__ out_val,
                       int Bn)
{
    extern __shared__ float smem[];
    float* feat = smem;                         // PB*1024
    float* w1T  = feat + PB*NFEAT;              // 32*1025
    float* w2s  = w1T + H1*W1TS;                // 1024
    float* x1s  = w2s + 1024;                   // PB*33
    float* b1s  = x1s + PB*X1S;                 // 32
    float* b2s  = b1s + 32;                     // 32
    float* w3s  = b2s + 32;                     // 32
    int*   idxs = (int*)(w3s + 32);             // PB*64

    const int tid  = threadIdx.x;
    const int lane = tid & 31;
    const int wid  = tid >> 5;

    // ---- one-time staging ----
    for (int e = tid; e < NFEAT * H1; e += NTHR) {
        int i = e >> 5;
        int j = e & 31;
        w1T[j * W1TS + i] = w1[e];
    }
    for (int e = tid; e < H1 * H1; e += NTHR) w2s[e] = w2[e];
    if (tid < 32) {
        b1s[tid] = b1[tid];
        b2s[tid] = b2[tid];
        w3s[tid] = w3[tid];
    }

    const int is64 = (__ldg((const int*)widx_raw + 1) == 0) ? 1 : 0;
    const float b3v = __ldg(b3);

    // gather mapping: 2 positions x 2 perspectives x 64 uint4-columns
    const int psub = tid >> 7;          // position sub-slot 0/1
    const int side = (tid >> 6) & 1;    // perspective
    const int c    = tid & 63;          // uint4 column (8 halves)
    const uint4* __restrict__ wfth4 = (const uint4*)g_wft_h;

    // bias: b_ft is 512 floats (shared by both perspectives) -> float4 index c*2, c*2+1
    float bias8[8];
    {
        const float4 bA = ((const float4*)b_ft)[c * 2];
        const float4 bB = ((const float4*)b_ft)[c * 2 + 1];
        bias8[0]=bA.x; bias8[1]=bA.y; bias8[2]=bA.z; bias8[3]=bA.w;
        bias8[4]=bB.x; bias8[5]=bB.y; bias8[6]=bB.z; bias8[7]=bB.w;
    }

    // contiguous position range per block
    const int grid = gridDim.x;
    const int base = Bn / grid, rem = Bn % grid;
    const int bid  = blockIdx.x;
    int start, count;
    if (bid < rem) { count = base + 1; start = bid * count; }
    else           { count = base;     start = rem * (base + 1) + (bid - rem) * base; }

    __syncthreads();

    for (int off = 0; off < count; off += PB) {
        const int pos0 = start + off;
        const int npos = (count - off < PB) ? (count - off) : PB;

        // ---- index load (premultiplied by ROW_U4) ----
        const int nIdx = npos * 64;
        for (int e = tid; e < nIdx; e += NTHR) {
            const int p = e >> 6, t = e & 63;
            const void* src = (t < 32) ? widx_raw : bidx_raw;
            const long long g = (long long)(pos0 + p) * NACT + (t & 31);
            int r;
            if (is64) r = (int)((const long long*)src)[g];
            else      r = ((const int*)src)[g];
            idxs[e] = r * ROW_U4;
        }
        __syncthreads();

        // ---- gather: 2 positions at a time via thread split; 8 uint4 loads in flight ----
        for (int p0 = 0; p0 < npos; p0 += 2) {
            const int p = p0 + psub;
            const bool has = p < npos;
            const int* __restrict__ ip = idxs + (has ? p : 0) * 64 + side * NACT;
            float acc[8];
            #pragma unroll
            for (int j = 0; j < 8; j++) acc[j] = bias8[j];

            #pragma unroll
            for (int a = 0; a < NACT; a += 8) {
                uint4 v[8];
                #pragma unroll
                for (int u = 0; u < 8; u++)
                    v[u] = wfth4[ip[a + u] + c];
                #pragma unroll
                for (int u = 0; u < 8; u++) {
                    float2 f0 = __half22float2(*(__half2*)&v[u].x);
                    float2 f1 = __half22float2(*(__half2*)&v[u].y);
                    float2 f2 = __half22float2(*(__half2*)&v[u].z);
                    float2 f3 = __half22float2(*(__half2*)&v[u].w);
                    acc[0] += f0.x; acc[1] += f0.y;
                    acc[2] += f1.x; acc[3] += f1.y;
                    acc[4] += f2.x; acc[5] += f2.y;
                    acc[6] += f3.x; acc[7] += f3.y;
                }
            }
            if (has) {
                #pragma unroll
                for (int j = 0; j < 8; j++) acc[j] = fmaxf(acc[j], 0.f);
                float4 o0 = make_float4(acc[0], acc[1], acc[2], acc[3]);
                float4 o1 = make_float4(acc[4], acc[5], acc[6], acc[7]);
                const int slot = side * 128 + c * 2;       // float4 slot in 1024-row
                ((float4*)(feat + p * NFEAT))[slot]     = o0;
                ((float4*)(feat + p * NFEAT))[slot + 1] = o1;
                float4* og = (float4*)(out_feat + (size_t)(pos0 + p) * NFEAT);
                og[slot]     = o0;
                og[slot + 1] = o1;
            }
        }
        __syncthreads();

        // ---- layer 1: warp w owns outputs 4w..4w+3, all PB positions in registers ----
        {
            const int j0 = wid * 4;
            float acc0[PB], acc1[PB], acc2[PB], acc3[PB];
            #pragma unroll
            for (int pp = 0; pp < PB; pp++) { acc0[pp]=0.f; acc1[pp]=0.f; acc2[pp]=0.f; acc3[pp]=0.f; }

            #pragma unroll
            for (int kk = 0; kk < 8; kk++) {        // i-chunks of 128
                float wr0[4], wr1[4], wr2[4], wr3[4];
                #pragma unroll
                for (int k = 0; k < 4; k++) {
                    const int i = lane + 32 * (4 * kk + k);
                    wr0[k] = w1T[(j0 + 0) * W1TS + i];
                    wr1[k] = w1T[(j0 + 1) * W1TS + i];
                    wr2[k] = w1T[(j0 + 2) * W1TS + i];
                    wr3[k] = w1T[(j0 + 3) * W1TS + i];
                }
                #pragma unroll
                for (int pp = 0; pp < PB; pp++) {
                    if (pp < npos) {
                        #pragma unroll
                        for (int k = 0; k < 4; k++) {
                            const float f = feat[pp * NFEAT + lane + 32 * (4 * kk + k)];
                            acc0[pp] = fmaf(f, wr0[k], acc0[pp]);
                            acc1[pp] = fmaf(f, wr1[k], acc1[pp]);
                            acc2[pp] = fmaf(f, wr2[k], acc2[pp]);
                            acc3[pp] = fmaf(f, wr3[k], acc3[pp]);
                        }
                    }
                }
            }
            #pragma unroll
            for (int pp = 0; pp < PB; pp++) {
                if (pp < npos) {
                    float s0 = acc0[pp], s1 = acc1[pp], s2 = acc2[pp], s3 = acc3[pp];
                    #pragma unroll
                    for (int o = 16; o; o >>= 1) {
                        s0 += __shfl_xor_sync(0xffffffffu, s0, o);
                        s1 += __shfl_xor_sync(0xffffffffu, s1, o);
                        s2 += __shfl_xor_sync(0xffffffffu, s2, o);
                        s3 += __shfl_xor_sync(0xffffffffu, s3, o);
                    }
                    if (lane == 0) {
                        x1s[pp * X1S + j0 + 0] = fmaxf(s0 + b1s[j0 + 0], 0.f);
                        x1s[pp * X1S + j0 + 1] = fmaxf(s1 + b1s[j0 + 1], 0.f);
                        x1s[pp * X1S + j0 + 2] = fmaxf(s2 + b1s[j0 + 2], 0.f);
                        x1s[pp * X1S + j0 + 3] = fmaxf(s3 + b1s[j0 + 3], 0.f);
                    }
                }
            }
        }
        __syncthreads();

        // ---- layers 2+3: one warp per position ----
        for (int p = wid; p < npos; p += 8) {
            float s = b2s[lane];
            #pragma unroll
            for (int i = 0; i < H1; i++)
                s = fmaf(x1s[p * X1S + i], w2s[i * H1 + lane], s);
            s = fmaxf(s, 0.f);
            float v = s * w3s[lane];
            #pragma unroll
            for (int o = 16; o; o >>= 1)
                v += __shfl_xor_sync(0xffffffffu, v, o);
            if (lane == 0)
                out_val[pos0 + p] = (v + b3v) * 100.0f;
        }
        __syncthreads();
    }
}

extern "C" void kernel_launch(void* const* d_in, const int* in_sizes, int n_in,
                              void* d_out, int out_size)
{
    (void)n_in; (void)out_size;
    const void*  widx = d_in[0];
    const void*  bidx = d_in[1];
    const float* w_ft = (const float*)d_in[2];
    const float* b_ft = (const float*)d_in[3];
    const float* w1   = (const float*)d_in[4];
    const float* b1   = (const float*)d_in[5];
    const float* w2   = (const float*)d_in[6];
    const float* b2   = (const float*)d_in[7];
    const float* w3   = (const float*)d_in[8];
    const float* b3   = (const float*)d_in[9];

    const int Bn = in_sizes[0] / NACT;

    float* out_feat = (float*)d_out;
    float* out_val  = out_feat + (size_t)Bn * NFEAT;

    cudaFuncSetAttribute(nnue_fused_kernel,
                         cudaFuncAttributeMaxDynamicSharedMemorySize,
                         SMEM_BYTES);

    int dev = 0, nsm = 148;
    cudaGetDevice(&dev);
    cudaDeviceGetAttribute(&nsm, cudaDevAttrMultiProcessorCount, dev);
    if (nsm <= 0) nsm = 148;
    int grid = nsm;
    if (grid > Bn) grid = Bn;

    convert_kernel<<<nsm * 2, 1024>>>((const float4*)w_ft);

    nnue_fused_kernel<<<grid, NTHR, SMEM_BYTES>>>(
        widx, bidx, b_ft, w1, b1, w2, b2, w3, b3,
        out_feat, out_val, Bn);
}

// round 9
// speedup vs baseline: 1.2819x; 1.1001x over previous
#include <cuda_runtime.h>
#include <cuda_fp16.h>
#include <cstddef>

// NNUE evaluator: fp16-converted feature table + fused eval kernel, 2 blocks/SM.
// d_in: 0 white_idx [B,32] (int32/int64 runtime detected)  1 black_idx
//       2 w_ft [45056,512] f32  3 b_ft[512]  4 w1[1024,32] 5 b1[32]
//       6 w2[32,32] 7 b2[32] 8 w3[32,1] 9 b3[1]
// d_out: features [B,1024] f32 followed by values [B] f32.

#define F_DIM    45056
#define ACCW     512
#define NFEAT    1024
#define NACT     32
#define H1       32
#define PB       16
#define PH       8
#define X1S      33
#define NTHR     256
#define ROW_U4   64            // uint4 (8 halves) per 512-wide row

// scratch: fp16 feature table (46 MB) + transposed w1 [32][1024]
__device__ __align__(16) __half g_wft_h[(size_t)F_DIM * ACCW];
__device__ __align__(16) float  g_w1t[H1 * NFEAT];

// smem: feat PB*1024 + w2s 1024 + x1s PB*33 + biases 96 + idxs PB*64
#define SMEM_FLOATS (PB*NFEAT + 1024 + PB*X1S + 96 + PB*64)
#define SMEM_BYTES  (SMEM_FLOATS * 4)

static __device__ __forceinline__ unsigned h2u(__half2 h) {
    unsigned u;
    memcpy(&u, &h, 4);
    return u;
}

// ---- conversion kernel: w_ft f32 -> fp16, plus w1 transpose ----
__global__ __launch_bounds__(1024, 2)
void convert_kernel(const float4* __restrict__ src, const float* __restrict__ w1)
{
    const int n8 = (F_DIM * ACCW) / 8;       // uint4 elements
    uint4* __restrict__ dst = (uint4*)g_wft_h;
    const int stride = gridDim.x * blockDim.x;
    for (int i = blockIdx.x * blockDim.x + threadIdx.x; i < n8; i += stride) {
        float4 a = src[2 * i];
        float4 b = src[2 * i + 1];
        uint4 o;
        o.x = h2u(__floats2half2_rn(a.x, a.y));
        o.y = h2u(__floats2half2_rn(a.z, a.w));
        o.z = h2u(__floats2half2_rn(b.x, b.y));
        o.w = h2u(__floats2half2_rn(b.z, b.w));
        dst[i] = o;
    }
    if (blockIdx.x == 0) {
        // transpose w1 [1024,32] -> g_w1t [32][1024]
        for (int e = threadIdx.x; e < NFEAT * H1; e += 1024)
            g_w1t[(e & 31) * NFEAT + (e >> 5)] = w1[e];
    }
}

__global__ __launch_bounds__(NTHR, 2)
void nnue_fused_kernel(const void* __restrict__ widx_raw,
                       const void* __restrict__ bidx_raw,
                       const float* __restrict__ b_ft,
                       const float* __restrict__ b1,
                       const float* __restrict__ w2,
                       const float* __restrict__ b2,
                       const float* __restrict__ w3,
                       const float* __restrict__ b3,
                       float* __restrict__ out_feat,
                       float* __restrict__ out_val,
                       int Bn)
{
    extern __shared__ float smem[];
    float* feat = smem;                         // PB*1024
    float* w2s  = feat + PB*NFEAT;              // 1024
    float* x1s  = w2s + 1024;                   // PB*33
    float* b1s  = x1s + PB*X1S;                 // 32
    float* b2s  = b1s + 32;                     // 32
    float* w3s  = b2s + 32;                     // 32
    int*   idxs = (int*)(w3s + 32);             // PB*64

    const int tid  = threadIdx.x;
    const int lane = tid & 31;
    const int wid  = tid >> 5;

    // ---- one-time staging ----
    for (int e = tid; e < H1 * H1; e += NTHR) w2s[e] = w2[e];
    if (tid < 32) {
        b1s[tid] = b1[tid];
        b2s[tid] = b2[tid];
        w3s[tid] = w3[tid];
    }

    const int is64 = (__ldg((const int*)widx_raw + 1) == 0) ? 1 : 0;
    const float b3v = __ldg(b3);

    // gather mapping: 2 positions x 2 perspectives x 64 uint4-columns
    const int psub = tid >> 7;
    const int side = (tid >> 6) & 1;
    const int c    = tid & 63;
    const uint4* __restrict__ wfth4 = (const uint4*)g_wft_h;

    float bias8[8];
    {
        const float4 bA = ((const float4*)b_ft)[c * 2];
        const float4 bB = ((const float4*)b_ft)[c * 2 + 1];
        bias8[0]=bA.x; bias8[1]=bA.y; bias8[2]=bA.z; bias8[3]=bA.w;
        bias8[4]=bB.x; bias8[5]=bB.y; bias8[6]=bB.z; bias8[7]=bB.w;
    }

    // contiguous position range per block
    const int grid = gridDim.x;
    const int base = Bn / grid, rem = Bn % grid;
    const int bid  = blockIdx.x;
    int start, count;
    if (bid < rem) { count = base + 1; start = bid * count; }
    else           { count = base;     start = rem * (base + 1) + (bid - rem) * base; }

    __syncthreads();

    for (int off = 0; off < count; off += PB) {
        const int pos0 = start + off;
        const int npos = (count - off < PB) ? (count - off) : PB;

        // ---- index load (premultiplied by ROW_U4) ----
        const int nIdx = npos * 64;
        for (int e = tid; e < nIdx; e += NTHR) {
            const int p = e >> 6, t = e & 63;
            const void* src = (t < 32) ? widx_raw : bidx_raw;
            const long long g = (long long)(pos0 + p) * NACT + (t & 31);
            int r;
            if (is64) r = (int)((const long long*)src)[g];
            else      r = ((const int*)src)[g];
            idxs[e] = r * ROW_U4;
        }
        __syncthreads();

        // ---- gather: 2 positions via thread split; 8 uint4 loads in flight ----
        for (int p0 = 0; p0 < npos; p0 += 2) {
            const int p = p0 + psub;
            const bool has = p < npos;
            const int* __restrict__ ip = idxs + (has ? p : 0) * 64 + side * NACT;
            float acc[8];
            #pragma unroll
            for (int j = 0; j < 8; j++) acc[j] = bias8[j];

            #pragma unroll
            for (int a = 0; a < NACT; a += 8) {
                uint4 v[8];
                #pragma unroll
                for (int u = 0; u < 8; u++)
                    v[u] = wfth4[ip[a + u] + c];
                #pragma unroll
                for (int u = 0; u < 8; u++) {
                    float2 f0 = __half22float2(*(__half2*)&v[u].x);
                    float2 f1 = __half22float2(*(__half2*)&v[u].y);
                    float2 f2 = __half22float2(*(__half2*)&v[u].z);
                    float2 f3 = __half22float2(*(__half2*)&v[u].w);
                    acc[0] += f0.x; acc[1] += f0.y;
                    acc[2] += f1.x; acc[3] += f1.y;
                    acc[4] += f2.x; acc[5] += f2.y;
                    acc[6] += f3.x; acc[7] += f3.y;
                }
            }
            if (has) {
                #pragma unroll
                for (int j = 0; j < 8; j++) acc[j] = fmaxf(acc[j], 0.f);
                float4 o0 = make_float4(acc[0], acc[1], acc[2], acc[3]);
                float4 o1 = make_float4(acc[4], acc[5], acc[6], acc[7]);
                const int slot = side * 128 + c * 2;
                ((float4*)(feat + p * NFEAT))[slot]     = o0;
                ((float4*)(feat + p * NFEAT))[slot + 1] = o1;
                float4* og = (float4*)(out_feat + (size_t)(pos0 + p) * NFEAT);
                og[slot]     = o0;
                og[slot + 1] = o1;
            }
        }
        __syncthreads();

        // ---- layer 1: warp w owns outputs 4w..4w+3; passes of PH positions.
        //      w1T rows come from global scratch (L1-resident). ----
        {
            const int j0 = wid * 4;
            const float* __restrict__ r0 = g_w1t + (j0 + 0) * NFEAT;
            const float* __restrict__ r1 = g_w1t + (j0 + 1) * NFEAT;
            const float* __restrict__ r2 = g_w1t + (j0 + 2) * NFEAT;
            const float* __restrict__ r3 = g_w1t + (j0 + 3) * NFEAT;

            for (int pbase = 0; pbase < npos; pbase += PH) {
                float acc0[PH], acc1[PH], acc2[PH], acc3[PH];
                #pragma unroll
                for (int pp = 0; pp < PH; pp++) { acc0[pp]=0.f; acc1[pp]=0.f; acc2[pp]=0.f; acc3[pp]=0.f; }

                #pragma unroll
                for (int kk = 0; kk < 8; kk++) {        // i-chunks of 128
                    float wr0[4], wr1[4], wr2[4], wr3[4];
                    #pragma unroll
                    for (int k = 0; k < 4; k++) {
                        const int i = lane + 32 * (4 * kk + k);
                        wr0[k] = __ldg(r0 + i);
                        wr1[k] = __ldg(r1 + i);
                        wr2[k] = __ldg(r2 + i);
                        wr3[k] = __ldg(r3 + i);
                    }
                    #pragma unroll
                    for (int pp = 0; pp < PH; pp++) {
                        const int p = pbase + pp;
                        if (p < npos) {
                            #pragma unroll
                            for (int k = 0; k < 4; k++) {
                                const float f = feat[p * NFEAT + lane + 32 * (4 * kk + k)];
                                acc0[pp] = fmaf(f, wr0[k], acc0[pp]);
                                acc1[pp] = fmaf(f, wr1[k], acc1[pp]);
                                acc2[pp] = fmaf(f, wr2[k], acc2[pp]);
                                acc3[pp] = fmaf(f, wr3[k], acc3[pp]);
                            }
                        }
                    }
                }
                #pragma unroll
                for (int pp = 0; pp < PH; pp++) {
                    const int p = pbase + pp;
                    if (p < npos) {
                        float s0 = acc0[pp], s1 = acc1[pp], s2 = acc2[pp], s3 = acc3[pp];
                        #pragma unroll
                        for (int o = 16; o; o >>= 1) {
                            s0 += __shfl_xor_sync(0xffffffffu, s0, o);
                            s1 += __shfl_xor_sync(0xffffffffu, s1, o);
                            s2 += __shfl_xor_sync(0xffffffffu, s2, o);
                            s3 += __shfl_xor_sync(0xffffffffu, s3, o);
                        }
                        if (lane == 0) {
                            x1s[p * X1S + j0 + 0] = fmaxf(s0 + b1s[j0 + 0], 0.f);
                            x1s[p * X1S + j0 + 1] = fmaxf(s1 + b1s[j0 + 1], 0.f);
                            x1s[p * X1S + j0 + 2] = fmaxf(s2 + b1s[j0 + 2], 0.f);
                            x1s[p * X1S + j0 + 3] = fmaxf(s3 + b1s[j0 + 3], 0.f);
                        }
                    }
                }
            }
        }
        __syncthreads();

        // ---- layers 2+3: one warp per position ----
        for (int p = wid; p < npos; p += 8) {
            float s = b2s[lane];
            #pragma unroll
            for (int i = 0; i < H1; i++)
                s = fmaf(x1s[p * X1S + i], w2s[i * H1 + lane], s);
            s = fmaxf(s, 0.f);
            float v = s * w3s[lane];
            #pragma unroll
            for (int o = 16; o; o >>= 1)
                v += __shfl_xor_sync(0xffffffffu, v, o);
            if (lane == 0)
                out_val[pos0 + p] = (v + b3v) * 100.0f;
        }
        __syncthreads();
    }
}

extern "C" void kernel_launch(void* const* d_in, const int* in_sizes, int n_in,
                              void* d_out, int out_size)
{
    (void)n_in; (void)out_size;
    const void*  widx = d_in[0];
    const void*  bidx = d_in[1];
    const float* w_ft = (const float*)d_in[2];
    const float* b_ft = (const float*)d_in[3];
    const float* w1   = (const float*)d_in[4];
    const float* b1   = (const float*)d_in[5];
    const float* w2   = (const float*)d_in[6];
    const float* b2   = (const float*)d_in[7];
    const float* w3   = (const float*)d_in[8];
    const float* b3   = (const float*)d_in[9];

    const int Bn = in_sizes[0] / NACT;

    float* out_feat = (float*)d_out;
    float* out_val  = out_feat + (size_t)Bn * NFEAT;

    cudaFuncSetAttribute(nnue_fused_kernel,
                         cudaFuncAttributeMaxDynamicSharedMemorySize,
                         SMEM_BYTES);

    int dev = 0, nsm = 148;
    cudaGetDevice(&dev);
    cudaDeviceGetAttribute(&nsm, cudaDevAttrMultiProcessorCount, dev);
    if (nsm <= 0) nsm = 148;
    int grid = nsm * 2;
    if (grid > Bn) grid = Bn;

    convert_kernel<<<nsm * 2, 1024>>>((const float4*)w_ft, w1);

    nnue_fused_kernel<<<grid, NTHR, SMEM_BYTES>>>(
        widx, bidx, b_ft, b1, w2, b2, w3, b3,
        out_feat, out_val, Bn);
}

// round 10
// speedup vs baseline: 1.3162x; 1.0267x over previous
#include <cuda_runtime.h>
#include <cuda_fp16.h>
#include <cstddef>

// NNUE evaluator: fp16-converted feature table + fused eval kernel, 2 blocks/SM.
// d_in: 0 white_idx [B,32] (int32/int64 runtime detected)  1 black_idx
//       2 w_ft [45056,512] f32  3 b_ft[512]  4 w1[1024,32] 5 b1[32]
//       6 w2[32,32] 7 b2[32] 8 w3[32,1] 9 b3[1]
// d_out: features [B,1024] f32 followed by values [B] f32.

#define F_DIM    45056
#define ACCW     512
#define NFEAT    1024
#define NACT     32
#define H1       32
#define PB       16
#define PH       8
#define X1S      33
#define NTHR     256
#define ROW_U4   64            // uint4 (8 halves) per 512-wide row

// scratch: fp16 feature table (46 MB) + transposed w1 [32][1024]
__device__ __align__(16) __half g_wft_h[(size_t)F_DIM * ACCW];
__device__ __align__(16) float  g_w1t[H1 * NFEAT];

// smem: feat PB*1024 + w2s 1024 + x1s PB*33 + biases 96 + idxs PB*64
#define SMEM_FLOATS (PB*NFEAT + 1024 + PB*X1S + 96 + PB*64)
#define SMEM_BYTES  (SMEM_FLOATS * 4)

static __device__ __forceinline__ unsigned h2u(__half2 h) {
    unsigned u;
    memcpy(&u, &h, 4);
    return u;
}

// ---- conversion kernel: w_ft f32 -> fp16 (streaming src, L2-resident dst) ----
__global__ __launch_bounds__(256, 8)
void convert_kernel(const float4* __restrict__ src, const float* __restrict__ w1)
{
    const int n8 = (F_DIM * ACCW) / 8;        // uint4 elements (2.88M)
    uint4* __restrict__ dst = (uint4*)g_wft_h;
    const int stride = gridDim.x * blockDim.x;
    const int t0 = blockIdx.x * blockDim.x + threadIdx.x;

    // 2 uint4 per iteration: 4 float4 streaming loads, 2 uint4 stores
    int i = t0 * 2;
    const int step = stride * 2;
    for (; i + 1 < n8; i += step) {
        float4 a0 = __ldcs(src + 2 * i);
        float4 b0 = __ldcs(src + 2 * i + 1);
        float4 a1 = __ldcs(src + 2 * i + 2);
        float4 b1 = __ldcs(src + 2 * i + 3);
        uint4 o0, o1;
        o0.x = h2u(__floats2half2_rn(a0.x, a0.y));
        o0.y = h2u(__floats2half2_rn(a0.z, a0.w));
        o0.z = h2u(__floats2half2_rn(b0.x, b0.y));
        o0.w = h2u(__floats2half2_rn(b0.z, b0.w));
        o1.x = h2u(__floats2half2_rn(a1.x, a1.y));
        o1.y = h2u(__floats2half2_rn(a1.z, a1.w));
        o1.z = h2u(__floats2half2_rn(b1.x, b1.y));
        o1.w = h2u(__floats2half2_rn(b1.z, b1.w));
        dst[i]     = o0;
        dst[i + 1] = o1;
    }
    if (i < n8) {   // n8 even, but keep the guard generic
        float4 a0 = __ldcs(src + 2 * i);
        float4 b0 = __ldcs(src + 2 * i + 1);
        uint4 o0;
        o0.x = h2u(__floats2half2_rn(a0.x, a0.y));
        o0.y = h2u(__floats2half2_rn(a0.z, a0.w));
        o0.z = h2u(__floats2half2_rn(b0.x, b0.y));
        o0.w = h2u(__floats2half2_rn(b0.z, b0.w));
        dst[i] = o0;
    }
    if (blockIdx.x == 0) {
        // transpose w1 [1024,32] -> g_w1t [32][1024]
        for (int e = threadIdx.x; e < NFEAT * H1; e += 256)
            g_w1t[(e & 31) * NFEAT + (e >> 5)] = w1[e];
    }
}

__global__ __launch_bounds__(NTHR, 2)
void nnue_fused_kernel(const void* __restrict__ widx_raw,
                       const void* __restrict__ bidx_raw,
                       const float* __restrict__ b_ft,
                       const float* __restrict__ b1,
                       const float* __restrict__ w2,
                       const float* __restrict__ b2,
                       const float* __restrict__ w3,
                       const float* __restrict__ b3,
                       float* __restrict__ out_feat,
                       float* __restrict__ out_val,
                       int Bn)
{
    extern __shared__ float smem[];
    float* feat = smem;                         // PB*1024
    float* w2s  = feat + PB*NFEAT;              // 1024
    float* x1s  = w2s + 1024;                   // PB*33
    float* b1s  = x1s + PB*X1S;                 // 32
    float* b2s  = b1s + 32;                     // 32
    float* w3s  = b2s + 32;                     // 32
    int*   idxs = (int*)(w3s + 32);             // PB*64

    const int tid  = threadIdx.x;
    const int lane = tid & 31;
    const int wid  = tid >> 5;

    // ---- one-time staging ----
    for (int e = tid; e < H1 * H1; e += NTHR) w2s[e] = w2[e];
    if (tid < 32) {
        b1s[tid] = b1[tid];
        b2s[tid] = b2[tid];
        w3s[tid] = w3[tid];
    }

    const int is64 = (__ldg((const int*)widx_raw + 1) == 0) ? 1 : 0;
    const float b3v = __ldg(b3);

    // gather mapping: 2 positions x 2 perspectives x 64 uint4-columns
    const int psub = tid >> 7;
    const int side = (tid >> 6) & 1;
    const int c    = tid & 63;
    const uint4* __restrict__ wfth4 = (const uint4*)g_wft_h;

    float bias8[8];
    {
        const float4 bA = ((const float4*)b_ft)[c * 2];
        const float4 bB = ((const float4*)b_ft)[c * 2 + 1];
        bias8[0]=bA.x; bias8[1]=bA.y; bias8[2]=bA.z; bias8[3]=bA.w;
        bias8[4]=bB.x; bias8[5]=bB.y; bias8[6]=bB.z; bias8[7]=bB.w;
    }

    // contiguous position range per block
    const int grid = gridDim.x;
    const int base = Bn / grid, rem = Bn % grid;
    const int bid  = blockIdx.x;
    int start, count;
    if (bid < rem) { count = base + 1; start = bid * count; }
    else           { count = base;     start = rem * (base + 1) + (bid - rem) * base; }

    __syncthreads();

    for (int off = 0; off < count; off += PB) {
        const int pos0 = start + off;
        const int npos = (count - off < PB) ? (count - off) : PB;

        // ---- index load (premultiplied by ROW_U4) ----
        const int nIdx = npos * 64;
        for (int e = tid; e < nIdx; e += NTHR) {
            const int p = e >> 6, t = e & 63;
            const void* src = (t < 32) ? widx_raw : bidx_raw;
            const long long g = (long long)(pos0 + p) * NACT + (t & 31);
            int r;
            if (is64) r = (int)((const long long*)src)[g];
            else      r = ((const int*)src)[g];
            idxs[e] = r * ROW_U4;
        }
        __syncthreads();

        // ---- gather: 2 positions via thread split; 8 uint4 loads in flight ----
        for (int p0 = 0; p0 < npos; p0 += 2) {
            const int p = p0 + psub;
            const bool has = p < npos;
            const int* __restrict__ ip = idxs + (has ? p : 0) * 64 + side * NACT;
            float acc[8];
            #pragma unroll
            for (int j = 0; j < 8; j++) acc[j] = bias8[j];

            #pragma unroll
            for (int a = 0; a < NACT; a += 8) {
                uint4 v[8];
                #pragma unroll
                for (int u = 0; u < 8; u++)
                    v[u] = wfth4[ip[a + u] + c];
                #pragma unroll
                for (int u = 0; u < 8; u++) {
                    float2 f0 = __half22float2(*(__half2*)&v[u].x);
                    float2 f1 = __half22float2(*(__half2*)&v[u].y);
                    float2 f2 = __half22float2(*(__half2*)&v[u].z);
                    float2 f3 = __half22float2(*(__half2*)&v[u].w);
                    acc[0] += f0.x; acc[1] += f0.y;
                    acc[2] += f1.x; acc[3] += f1.y;
                    acc[4] += f2.x; acc[5] += f2.y;
                    acc[6] += f3.x; acc[7] += f3.y;
                }
            }
            if (has) {
                #pragma unroll
                for (int j = 0; j < 8; j++) acc[j] = fmaxf(acc[j], 0.f);
                float4 o0 = make_float4(acc[0], acc[1], acc[2], acc[3]);
                float4 o1 = make_float4(acc[4], acc[5], acc[6], acc[7]);
                const int slot = side * 128 + c * 2;
                ((float4*)(feat + p * NFEAT))[slot]     = o0;
                ((float4*)(feat + p * NFEAT))[slot + 1] = o1;
                float4* og = (float4*)(out_feat + (size_t)(pos0 + p) * NFEAT);
                og[slot]     = o0;
                og[slot + 1] = o1;
            }
        }
        __syncthreads();

        // ---- layer 1: warp w owns outputs 4w..4w+3; passes of PH positions.
        //      w1T rows come from global scratch (L1-resident). ----
        {
            const int j0 = wid * 4;
            const float* __restrict__ r0 = g_w1t + (j0 + 0) * NFEAT;
            const float* __restrict__ r1 = g_w1t + (j0 + 1) * NFEAT;
            const float* __restrict__ r2 = g_w1t + (j0 + 2) * NFEAT;
            const float* __restrict__ r3 = g_w1t + (j0 + 3) * NFEAT;

            for (int pbase = 0; pbase < npos; pbase += PH) {
                float acc0[PH], acc1[PH], acc2[PH], acc3[PH];
                #pragma unroll
                for (int pp = 0; pp < PH; pp++) { acc0[pp]=0.f; acc1[pp]=0.f; acc2[pp]=0.f; acc3[pp]=0.f; }

                #pragma unroll
                for (int kk = 0; kk < 8; kk++) {        // i-chunks of 128
                    float wr0[4], wr1[4], wr2[4], wr3[4];
                    #pragma unroll
                    for (int k = 0; k < 4; k++) {
                        const int i = lane + 32 * (4 * kk + k);
                        wr0[k] = __ldg(r0 + i);
                        wr1[k] = __ldg(r1 + i);
                        wr2[k] = __ldg(r2 + i);
                        wr3[k] = __ldg(r3 + i);
                    }
                    #pragma unroll
                    for (int pp = 0; pp < PH; pp++) {
                        const int p = pbase + pp;
                        if (p < npos) {
                            #pragma unroll
                            for (int k = 0; k < 4; k++) {
                                const float f = feat[p * NFEAT + lane + 32 * (4 * kk + k)];
                                acc0[pp] = fmaf(f, wr0[k], acc0[pp]);
                                acc1[pp] = fmaf(f, wr1[k], acc1[pp]);
                                acc2[pp] = fmaf(f, wr2[k], acc2[pp]);
                                acc3[pp] = fmaf(f, wr3[k], acc3[pp]);
                            }
                        }
                    }
                }
                #pragma unroll
                for (int pp = 0; pp < PH; pp++) {
                    const int p = pbase + pp;
                    if (p < npos) {
                        float s0 = acc0[pp], s1 = acc1[pp], s2 = acc2[pp], s3 = acc3[pp];
                        #pragma unroll
                        for (int o = 16; o; o >>= 1) {
                            s0 += __shfl_xor_sync(0xffffffffu, s0, o);
                            s1 += __shfl_xor_sync(0xffffffffu, s1, o);
                            s2 += __shfl_xor_sync(0xffffffffu, s2, o);
                            s3 += __shfl_xor_sync(0xffffffffu, s3, o);
                        }
                        if (lane == 0) {
                            x1s[p * X1S + j0 + 0] = fmaxf(s0 + b1s[j0 + 0], 0.f);
                            x1s[p * X1S + j0 + 1] = fmaxf(s1 + b1s[j0 + 1], 0.f);
                            x1s[p * X1S + j0 + 2] = fmaxf(s2 + b1s[j0 + 2], 0.f);
                            x1s[p * X1S + j0 + 3] = fmaxf(s3 + b1s[j0 + 3], 0.f);
                        }
                    }
                }
            }
        }
        __syncthreads();

        // ---- layers 2+3: one warp per position ----
        for (int p = wid; p < npos; p += 8) {
            float s = b2s[lane];
            #pragma unroll
            for (int i = 0; i < H1; i++)
                s = fmaf(x1s[p * X1S + i], w2s[i * H1 + lane], s);
            s = fmaxf(s, 0.f);
            float v = s * w3s[lane];
            #pragma unroll
            for (int o = 16; o; o >>= 1)
                v += __shfl_xor_sync(0xffffffffu, v, o);
            if (lane == 0)
                out_val[pos0 + p] = (v + b3v) * 100.0f;
        }
        __syncthreads();
    }
}

extern "C" void kernel_launch(void* const* d_in, const int* in_sizes, int n_in,
                              void* d_out, int out_size)
{
    (void)n_in; (void)out_size;
    const void*  widx = d_in[0];
    const void*  bidx = d_in[1];
    const float* w_ft = (const float*)d_in[2];
    const float* b_ft = (const float*)d_in[3];
    const float* w1   = (const float*)d_in[4];
    const float* b1   = (const float*)d_in[5];
    const float* w2   = (const float*)d_in[6];
    const float* b2   = (const float*)d_in[7];
    const float* w3   = (const float*)d_in[8];
    const float* b3   = (const float*)d_in[9];

    const int Bn = in_sizes[0] / NACT;

    float* out_feat = (float*)d_out;
    float* out_val  = out_feat + (size_t)Bn * NFEAT;

    cudaFuncSetAttribute(nnue_fused_kernel,
                         cudaFuncAttributeMaxDynamicSharedMemorySize,
                         SMEM_BYTES);

    int dev = 0, nsm = 148;
    cudaGetDevice(&dev);
    cudaDeviceGetAttribute(&nsm, cudaDevAttrMultiProcessorCount, dev);
    if (nsm <= 0) nsm = 148;
    int grid = nsm * 2;
    if (grid > Bn) grid = Bn;

    convert_kernel<<<nsm * 8, 256>>>((const float4*)w_ft, w1);

    nnue_fused_kernel<<<grid, NTHR, SMEM_BYTES>>>(
        widx, bidx, b_ft, b1, w2, b2, w3, b3,
        out_feat, out_val, Bn);
}

// round 11
// speedup vs baseline: 1.9031x; 1.4459x over previous
#include <cuda_runtime.h>
#include <cstddef>

// NNUE evaluator: direct fp32 gather, w1 transposed to global scratch,
// 2 blocks/SM eval kernel. No table conversion pass.
// d_in: 0 white_idx [B,32] (int32/int64 runtime detected)  1 black_idx
//       2 w_ft [45056,512] f32  3 b_ft[512]  4 w1[1024,32] 5 b1[32]
//       6 w2[32,32] 7 b2[32] 8 w3[32,1] 9 b3[1]
// d_out: features [B,1024] f32 followed by values [B] f32.

#define F_DIM    45056
#define NC4      128          // float4 per 512-wide perspective row
#define NFEAT    1024
#define NACT     32
#define H1       32
#define PB       16
#define PH       8
#define X1S      33
#define NTHR     256

// scratch: transposed w1 [32][1024]
__device__ __align__(16) float g_w1t[H1 * NFEAT];

// smem: feat PB*1024 + w2s 1024 + x1s PB*33 + biases 96 + idxs PB*64
#define SMEM_FLOATS (PB*NFEAT + 1024 + PB*X1S + 96 + PB*64)
#define SMEM_BYTES  (SMEM_FLOATS * 4)

// ---- tiny prep kernel: transpose w1 [1024,32] -> g_w1t [32][1024] ----
__global__ void w1_transpose_kernel(const float* __restrict__ w1)
{
    const int e = blockIdx.x * blockDim.x + threadIdx.x;
    if (e < NFEAT * H1)
        g_w1t[(e & 31) * NFEAT + (e >> 5)] = w1[e];
}

__global__ __launch_bounds__(NTHR, 2)
void nnue_fused_kernel(const void* __restrict__ widx_raw,
                       const void* __restrict__ bidx_raw,
                       const float* __restrict__ w_ft,
                       const float* __restrict__ b_ft,
                       const float* __restrict__ b1,
                       const float* __restrict__ w2,
                       const float* __restrict__ b2,
                       const float* __restrict__ w3,
                       const float* __restrict__ b3,
                       float* __restrict__ out_feat,
                       float* __restrict__ out_val,
                       int Bn)
{
    extern __shared__ float smem[];
    float* feat = smem;                         // PB*1024
    float* w2s  = feat + PB*NFEAT;              // 1024
    float* x1s  = w2s + 1024;                   // PB*33
    float* b1s  = x1s + PB*X1S;                 // 32
    float* b2s  = b1s + 32;                     // 32
    float* w3s  = b2s + 32;                     // 32
    int*   idxs = (int*)(w3s + 32);             // PB*64

    const int tid  = threadIdx.x;
    const int lane = tid & 31;
    const int wid  = tid >> 5;

    // ---- one-time staging ----
    for (int e = tid; e < H1 * H1; e += NTHR) w2s[e] = w2[e];
    if (tid < 32) {
        b1s[tid] = b1[tid];
        b2s[tid] = b2[tid];
        w3s[tid] = w3[tid];
    }

    const int is64 = (__ldg((const int*)widx_raw + 1) == 0) ? 1 : 0;
    const float b3v = __ldg(b3);

    const int side = tid >> 7;       // perspective
    const int c    = tid & 127;      // float4 column within perspective
    const float4* __restrict__ wft4 = (const float4*)w_ft;
    const float4 bias = ((const float4*)b_ft)[c];

    // contiguous position range per block
    const int grid = gridDim.x;
    const int base = Bn / grid, rem = Bn % grid;
    const int bid  = blockIdx.x;
    int start, count;
    if (bid < rem) { count = base + 1; start = bid * count; }
    else           { count = base;     start = rem * (base + 1) + (bid - rem) * base; }

    __syncthreads();

    for (int off = 0; off < count; off += PB) {
        const int pos0 = start + off;
        const int npos = (count - off < PB) ? (count - off) : PB;

        // ---- index load (premultiplied by NC4) ----
        const int nIdx = npos * 64;
        for (int e = tid; e < nIdx; e += NTHR) {
            const int p = e >> 6, t = e & 63;
            const void* src = (t < 32) ? widx_raw : bidx_raw;
            const long long g = (long long)(pos0 + p) * NACT + (t & 31);
            int r;
            if (is64) r = (int)((const long long*)src)[g];
            else      r = ((const int*)src)[g];
            idxs[e] = r * NC4;
        }
        __syncthreads();

        // ---- gather: 2 positions interleaved, 8 LDG.128 in flight ----
        for (int p0 = 0; p0 < npos; p0 += 2) {
            const bool has2 = (p0 + 1 < npos);
            const int* __restrict__ i0 = idxs + p0 * 64 + side * NACT;
            const int* __restrict__ i1 = idxs + (has2 ? p0 + 1 : p0) * 64 + side * NACT;
            float4 a0 = bias, a1 = bias;
            #pragma unroll
            for (int a = 0; a < NACT; a += 4) {
                float4 v0[4], v1[4];
                #pragma unroll
                for (int u = 0; u < 4; u++) v0[u] = wft4[i0[a + u] + c];
                #pragma unroll
                for (int u = 0; u < 4; u++) v1[u] = wft4[i1[a + u] + c];
                #pragma unroll
                for (int u = 0; u < 4; u++) {
                    a0.x += v0[u].x; a0.y += v0[u].y; a0.z += v0[u].z; a0.w += v0[u].w;
                    a1.x += v1[u].x; a1.y += v1[u].y; a1.z += v1[u].z; a1.w += v1[u].w;
                }
            }
            a0.x = fmaxf(a0.x, 0.f); a0.y = fmaxf(a0.y, 0.f);
            a0.z = fmaxf(a0.z, 0.f); a0.w = fmaxf(a0.w, 0.f);
            ((float4*)feat)[p0 * 256 + tid] = a0;
            ((float4*)(out_feat + (size_t)(pos0 + p0) * NFEAT))[tid] = a0;
            if (has2) {
                a1.x = fmaxf(a1.x, 0.f); a1.y = fmaxf(a1.y, 0.f);
                a1.z = fmaxf(a1.z, 0.f); a1.w = fmaxf(a1.w, 0.f);
                ((float4*)feat)[(p0 + 1) * 256 + tid] = a1;
                ((float4*)(out_feat + (size_t)(pos0 + p0 + 1) * NFEAT))[tid] = a1;
            }
        }
        __syncthreads();

        // ---- layer 1: warp w owns outputs 4w..4w+3; passes of PH positions.
        //      w1T rows from global scratch (L1-resident). ----
        {
            const int j0 = wid * 4;
            const float* __restrict__ r0 = g_w1t + (j0 + 0) * NFEAT;
            const float* __restrict__ r1 = g_w1t + (j0 + 1) * NFEAT;
            const float* __restrict__ r2 = g_w1t + (j0 + 2) * NFEAT;
            const float* __restrict__ r3 = g_w1t + (j0 + 3) * NFEAT;

            for (int pbase = 0; pbase < npos; pbase += PH) {
                float acc0[PH], acc1[PH], acc2[PH], acc3[PH];
                #pragma unroll
                for (int pp = 0; pp < PH; pp++) { acc0[pp]=0.f; acc1[pp]=0.f; acc2[pp]=0.f; acc3[pp]=0.f; }

                #pragma unroll
                for (int kk = 0; kk < 8; kk++) {        // i-chunks of 128
                    float wr0[4], wr1[4], wr2[4], wr3[4];
                    #pragma unroll
                    for (int k = 0; k < 4; k++) {
                        const int i = lane + 32 * (4 * kk + k);
                        wr0[k] = __ldg(r0 + i);
                        wr1[k] = __ldg(r1 + i);
                        wr2[k] = __ldg(r2 + i);
                        wr3[k] = __ldg(r3 + i);
                    }
                    #pragma unroll
                    for (int pp = 0; pp < PH; pp++) {
                        const int p = pbase + pp;
                        if (p < npos) {
                            #pragma unroll
                            for (int k = 0; k < 4; k++) {
                                const float f = feat[p * NFEAT + lane + 32 * (4 * kk + k)];
                                acc0[pp] = fmaf(f, wr0[k], acc0[pp]);
                                acc1[pp] = fmaf(f, wr1[k], acc1[pp]);
                                acc2[pp] = fmaf(f, wr2[k], acc2[pp]);
                                acc3[pp] = fmaf(f, wr3[k], acc3[pp]);
                            }
                        }
                    }
                }
                #pragma unroll
                for (int pp = 0; pp < PH; pp++) {
                    const int p = pbase + pp;
                    if (p < npos) {
                        float s0 = acc0[pp], s1 = acc1[pp], s2 = acc2[pp], s3 = acc3[pp];
                        #pragma unroll
                        for (int o = 16; o; o >>= 1) {
                            s0 += __shfl_xor_sync(0xffffffffu, s0, o);
                            s1 += __shfl_xor_sync(0xffffffffu, s1, o);
                            s2 += __shfl_xor_sync(0xffffffffu, s2, o);
                            s3 += __shfl_xor_sync(0xffffffffu, s3, o);
                        }
                        if (lane == 0) {
                            x1s[p * X1S + j0 + 0] = fmaxf(s0 + b1s[j0 + 0], 0.f);
                            x1s[p * X1S + j0 + 1] = fmaxf(s1 + b1s[j0 + 1], 0.f);
                            x1s[p * X1S + j0 + 2] = fmaxf(s2 + b1s[j0 + 2], 0.f);
                            x1s[p * X1S + j0 + 3] = fmaxf(s3 + b1s[j0 + 3], 0.f);
                        }
                    }
                }
            }
        }
        __syncthreads();

        // ---- layers 2+3: one warp per position ----
        for (int p = wid; p < npos; p += 8) {
            float s = b2s[lane];
            #pragma unroll
            for (int i = 0; i < H1; i++)
                s = fmaf(x1s[p * X1S + i], w2s[i * H1 + lane], s);
            s = fmaxf(s, 0.f);
            float v = s * w3s[lane];
            #pragma unroll
            for (int o = 16; o; o >>= 1)
                v += __shfl_xor_sync(0xffffffffu, v, o);
            if (lane == 0)
                out_val[pos0 + p] = (v + b3v) * 100.0f;
        }
        __syncthreads();
    }
}

extern "C" void kernel_launch(void* const* d_in, const int* in_sizes, int n_in,
                              void* d_out, int out_size)
{
    (void)n_in; (void)out_size;
    const void*  widx = d_in[0];
    const void*  bidx = d_in[1];
    const float* w_ft = (const float*)d_in[2];
    const float* b_ft = (const float*)d_in[3];
    const float* w1   = (const float*)d_in[4];
    const float* b1   = (const float*)d_in[5];
    const float* w2   = (const float*)d_in[6];
    const float* b2   = (const float*)d_in[7];
    const float* w3   = (const float*)d_in[8];
    const float* b3   = (const float*)d_in[9];

    const int Bn = in_sizes[0] / NACT;

    float* out_feat = (float*)d_out;
    float* out_val  = out_feat + (size_t)Bn * NFEAT;

    cudaFuncSetAttribute(nnue_fused_kernel,
                         cudaFuncAttributeMaxDynamicSharedMemorySize,
                         SMEM_BYTES);

    int dev = 0, nsm = 148;
    cudaGetDevice(&dev);
    cudaDeviceGetAttribute(&nsm, cudaDevAttrMultiProcessorCount, dev);
    if (nsm <= 0) nsm = 148;
    int grid = nsm * 2;
    if (grid > Bn) grid = Bn;

    w1_transpose_kernel<<<(NFEAT * H1 + 255) / 256, 256>>>(w1);

    nnue_fused_kernel<<<grid, NTHR, SMEM_BYTES>>>(
        widx, bidx, w_ft, b_ft, b1, w2, b2, w3, b3,
        out_feat, out_val, Bn);
}